// round 5
// baseline (speedup 1.0000x reference)
#include <cuda_runtime.h>
#include <cstdint>

// inv[n] = most-recent j with idx[j]==n, else -1. next[j] = previous winner
// for the same column (duplicate chain), else -1. bits: 1 bit per column.
#define INV_CAP (1 << 20)
__device__ int g_inv[INV_CAP];
__device__ int g_next[INV_CAP];
__device__ unsigned int g_bits[INV_CAP / 32];

__device__ __forceinline__ bool detect_is64(const unsigned int* w, int K) {
    // int64 small non-negative indices => all odd 32-bit words are zero.
    if (K >= 8) return ((w[1] | w[3] | w[5] | w[7]) == 0u);
    if (K >= 2) return (w[1] == 0u);
    return false;
}

__device__ __forceinline__ int load_idx(const void* idx_raw, int j, bool is64) {
    return is64 ? (int)((const long long*)idx_raw)[j]
                : ((const int*)idx_raw)[j];
}

// One launch: clear inv[0..N) to -1 and bits[0..ceil(N/32)) to 0.
__global__ void init_maps_kernel(int n, int nwords) {
    int i = blockIdx.x * blockDim.x + threadIdx.x;
    if (i < n) g_inv[i] = -1;
    if (i < nwords) g_bits[i] = 0u;
}

__global__ void build_inv_kernel(const void* __restrict__ idx_raw, int K) {
    int j = blockIdx.x * blockDim.x + threadIdx.x;
    if (j >= K) return;
    bool is64 = detect_is64((const unsigned int*)idx_raw, K);
    int col = load_idx(idx_raw, j, is64);
    int old = atomicExch(&g_inv[col], j);
    g_next[j] = old;                       // duplicate chain (usually -1)
    atomicOr(&g_bits[col >> 5], 1u << (col & 31));
}

__device__ __forceinline__ float chain_sum(const float* __restrict__ rb, int j) {
    float v = 0.f;
    while (j >= 0) { v += __ldg(rb + j); j = g_next[j]; }
    return v;
}

// Single streaming pass: each thread owns one 4-column group across
// rows_per_thread batch rows. Bitmap decides hit/miss without touching inv.
__global__ void fused_write_kernel(const float* __restrict__ in,
                                   float* __restrict__ out,
                                   int B, int N, int K, int rows_per_thread,
                                   int vec_ok) {
    int n_groups = (N + 3) >> 2;
    int g = blockIdx.x * blockDim.x + threadIdx.x;
    if (g >= n_groups) return;
    int n0 = g * 4;

    int b0 = blockIdx.y * rows_per_thread;
    int bend = b0 + rows_per_thread;
    if (bend > B) bend = B;

    if (vec_ok && n0 + 4 <= N) {
        unsigned int word = __ldg(&g_bits[n0 >> 5]);
        unsigned int hit4 = (word >> (n0 & 31)) & 0xFu;
        float4 z = make_float4(0.f, 0.f, 0.f, 0.f);
        if (hit4 == 0u) {
            #pragma unroll 4
            for (int b = b0; b < bend; b++) {
                float4* p = reinterpret_cast<float4*>(out + (long long)b * N + n0);
                __stcs(p, z);
            }
        } else {
            int4 iv = *reinterpret_cast<const int4*>(&g_inv[n0]);
            for (int b = b0; b < bend; b++) {
                const float* rb = in + (long long)b * K;
                float4 v;
                v.x = (iv.x >= 0) ? chain_sum(rb, iv.x) : 0.f;
                v.y = (iv.y >= 0) ? chain_sum(rb, iv.y) : 0.f;
                v.z = (iv.z >= 0) ? chain_sum(rb, iv.z) : 0.f;
                v.w = (iv.w >= 0) ? chain_sum(rb, iv.w) : 0.f;
                float4* p = reinterpret_cast<float4*>(out + (long long)b * N + n0);
                __stcs(p, v);
            }
        }
    } else {
        // Scalar tail / unaligned fallback (still duplicate-exact via chain).
        for (int c = n0; c < n0 + 4 && c < N; c++) {
            int j = g_inv[c];
            for (int b = b0; b < bend; b++) {
                const float* rb = in + (long long)b * K;
                float v = (j >= 0) ? chain_sum(rb, j) : 0.f;
                out[(long long)b * N + c] = v;
            }
        }
    }
}

// ---- Fallback path (N too large for inv map): fill + atomic scatter ----
__global__ void zero_fill_kernel(float4* __restrict__ out4, long long n4) {
    long long i = (long long)blockIdx.x * blockDim.x + threadIdx.x;
    long long stride = (long long)gridDim.x * blockDim.x;
    float4 z = make_float4(0.f, 0.f, 0.f, 0.f);
    for (; i < n4; i += stride) out4[i] = z;
}

__global__ void scatter_add_kernel(const float* __restrict__ in,
                                   const void* __restrict__ idx_raw,
                                   float* __restrict__ out,
                                   int B, int K, long long N) {
    long long t = (long long)blockIdx.x * blockDim.x + threadIdx.x;
    long long total = (long long)B * K;
    if (t >= total) return;
    int b = (int)(t / K);
    int j = (int)(t % K);
    bool is64 = detect_is64((const unsigned int*)idx_raw, K);
    long long col = load_idx(idx_raw, j, is64);
    atomicAdd(&out[(long long)b * N + col], in[(long long)b * K + j]);
}

extern "C" void kernel_launch(void* const* d_in, const int* in_sizes, int n_in,
                              void* d_out, int out_size) {
    const float* inputs = (const float*)d_in[0];
    const void* idx = d_in[1];
    float* out = (float*)d_out;

    int total_in = in_sizes[0];   // B * K
    int K = in_sizes[1];          // observed count
    int B = total_in / K;
    long long Nll = (long long)out_size / B;
    int N = (int)Nll;

    if (Nll <= INV_CAP && K <= INV_CAP) {
        int nwords = (N + 31) / 32;
        init_maps_kernel<<<(N + 255) / 256, 256>>>(N, nwords);
        build_inv_kernel<<<(K + 255) / 256, 256>>>(idx, K);

        const int ROWS = 8;
        int n_groups = (N + 3) / 4;
        int vec_ok = ((N & 3) == 0) ? 1 : 0;
        dim3 block(256, 1, 1);
        dim3 grid((n_groups + 255) / 256, (B + ROWS - 1) / ROWS, 1);
        fused_write_kernel<<<grid, block>>>(inputs, out, B, N, K, ROWS, vec_ok);
    } else {
        // Fallback: zero-fill + atomic scatter.
        long long n4 = (long long)out_size / 4;
        int threads = 256;
        long long blocks_ll = (n4 + threads - 1) / threads;
        int blocks = (blocks_ll > 0x7FFFFFF0LL) ? 0x7FFFFFF0 : (int)blocks_ll;
        zero_fill_kernel<<<blocks, threads>>>((float4*)out, n4);
        long long tail_start = n4 * 4;
        if (tail_start < (long long)out_size) {
            cudaMemsetAsync(out + tail_start, 0,
                            ((long long)out_size - tail_start) * sizeof(float), 0);
        }
        long long total = (long long)B * K;
        int sblocks = (int)((total + threads - 1) / threads);
        scatter_add_kernel<<<sblocks, threads>>>(inputs, idx, out, B, K, Nll);
    }
}